// round 10
// baseline (speedup 1.0000x reference)
#include <cuda_runtime.h>
#include <math.h>

#define Bsz 512
#define Tt  1024
#define Dd  64
#define Hh  64
#define Rr  4
#define MHh 32
#define PCH 16

typedef unsigned long long ull;

// xg scratch, plain row order: xg[t][b][row], bias baked in. 512MB.
__device__ float xg_buf[(size_t)Tt * Bsz * 256];

__device__ __forceinline__ void fma2(ull &d, ull a, ull b){
    asm("fma.rn.f32x2 %0, %1, %2, %0;" : "+l"(d) : "l"(a), "l"(b));
}
__device__ __forceinline__ ull pack2(float lo, float hi){
    ull r; asm("mov.b64 %0, {%1, %2};" : "=l"(r) : "f"(lo), "f"(hi)); return r;
}
__device__ __forceinline__ float2 unpack2(ull v){
    float2 r; asm("mov.b64 {%0, %1}, %2;" : "=f"(r.x), "=f"(r.y) : "l"(v)); return r;
}

__device__ __forceinline__ float fsigmoid(float v){
    float e = __expf(-v);
    return __fdividef(1.0f, 1.0f + e);
}
// Saturation-safe: exp argument always <= 0.
__device__ __forceinline__ float ftanh(float v){
    float t = __expf(-2.0f * fabsf(v));
    float r = __fdividef(1.0f - t, 1.0f + t);
    return copysignf(r, v);
}

// ---------------------------------------------------------------------------
// Input projection (unchanged): thread j owns rows 2j, 2j+1.
// ---------------------------------------------------------------------------
__global__ __launch_bounds__(128)
void proj_kernel(const float* __restrict__ x,
                 const float* __restrict__ W_ih,
                 const float* __restrict__ b_ih,
                 const float* __restrict__ b_hh)
{
    const int j  = threadIdx.x;
    const int r0 = 2*j, r1 = 2*j + 1;
    const int b  = blockIdx.x >> 2;
    const int t0 = (blockIdx.x & 3) * 256;

    __shared__ __align__(16) float xsh[PCH][Dd];

    ull w0[Dd/2], w1[Dd/2];
#pragma unroll
    for (int k = 0; k < Dd/2; k += 2){
        ulonglong2 a = *(const ulonglong2*)&W_ih[r0 * Dd + 2*k];
        w0[k] = a.x; w0[k+1] = a.y;
        ulonglong2 c = *(const ulonglong2*)&W_ih[r1 * Dd + 2*k];
        w1[k] = c.x; w1[k+1] = c.y;
    }
    const float bj0 = b_ih[r0] + b_hh[r0];
    const float bj1 = b_ih[r1] + b_hh[r1];

    for (int c0 = 0; c0 < 256; c0 += PCH){
        const float4* src = (const float4*)(x + ((size_t)b * Tt + t0 + c0) * Dd);
        float4* dst = (float4*)&xsh[0][0];
        dst[j] = src[j];
        dst[j + 128] = src[j + 128];
        __syncthreads();

#pragma unroll 2
        for (int p = 0; p < PCH; p++){
            const ulonglong2* v = (const ulonglong2*)&xsh[p][0];
            ull a00 = 0ULL, a01 = 0ULL, a10 = 0ULL, a11 = 0ULL;
#pragma unroll
            for (int q = 0; q < 16; q++){
                ulonglong2 xx = v[q];
                fma2(a00, w0[2*q    ], xx.x);
                fma2(a01, w0[2*q + 1], xx.y);
                fma2(a10, w1[2*q    ], xx.x);
                fma2(a11, w1[2*q + 1], xx.y);
            }
            float2 p0 = unpack2(a00), p1 = unpack2(a01);
            float2 p2 = unpack2(a10), p3 = unpack2(a11);
            size_t base = ((size_t)(t0 + c0 + p) * Bsz + b) * 256;
            float2 o;
            o.x = bj0 + ((p0.x + p1.x) + (p0.y + p1.y));
            o.y = bj1 + ((p2.x + p3.x) + (p2.y + p3.y));
            *(float2*)&xg_buf[base + 2*j] = o;
        }
        __syncthreads();
    }
}

// ---------------------------------------------------------------------------
// Recurrence v4: 512 blocks x 128 threads, ONE batch per block -> ~3.5
// independent serial chains per SM. Warp w covers units 16w..16w+15.
// Lane l<16: rows (i,g) of unit u. Lane l>=16: rows (f,o) of unit u (=l^16's
// unit). Gate exchange = 2x shfl_xor(16); both halves compute the identical
// state update (redundant, cheap); half0 stores hs, half1 stores y.
// hs double-buffered -> ONE __syncthreads per step.
// ---------------------------------------------------------------------------
__global__ __launch_bounds__(128, 8)
void lstm_rec_kernel(const float* __restrict__ h_init,
                     const float* __restrict__ c_init,
                     const float* __restrict__ W_hh,
                     float* __restrict__ y)
{
    const int tid  = threadIdx.x;
    const int w    = tid >> 5;
    const int l    = tid & 31;
    const int half = l >> 4;               // 0: rows (i,g); 1: rows (f,o)
    const int u    = (w << 4) + (l & 15);  // unit 0..63
    const int rA   = half ? (64 + u) : u;          // f : i
    const int rB   = half ? (192 + u) : (128 + u); // o : g
    const int b    = blockIdx.x;            // batch

    __shared__ __align__(16) float hs[2][Hh];

    ull wA[Hh/2], wB[Hh/2];
#pragma unroll
    for (int k = 0; k < Hh/2; k += 2){
        ulonglong2 a = *(const ulonglong2*)&W_hh[rA * Hh + 2*k];
        wA[k] = a.x; wA[k+1] = a.y;
        ulonglong2 c = *(const ulonglong2*)&W_hh[rB * Hh + 2*k];
        wB[k] = c.x; wB[k+1] = c.y;
    }

    float creg = c_init[u];                // state (unit u) — kept by BOTH halves
    if (half == 0) hs[0][u] = h_init[u];

    float xA = xg_buf[(size_t)b * 256 + rA];
    float xB = xg_buf[(size_t)b * 256 + rB];
    __syncthreads();

    float* yrow = y + (size_t)b * Tt * Hh + u;

#pragma unroll 1
    for (int t = 0; t < Tt; t++){
        const int pr = t & 1;
        float cA = xA, cB = xB;
        if (t + 1 < Tt){
            size_t base = ((size_t)(t + 1) * Bsz + b) * 256;
            xA = xg_buf[base + rA];
            xB = xg_buf[base + rB];
        }

        ull aAa = 0ULL, aAb = 0ULL, aBa = 0ULL, aBb = 0ULL;
#pragma unroll
        for (int k = 0; k < Hh; k += 4){
            ulonglong2 v = *(const ulonglong2*)&hs[pr][k];   // broadcast LDS.128
            fma2(aAa, wA[k/2    ], v.x);
            fma2(aAb, wA[k/2 + 1], v.y);
            fma2(aBa, wB[k/2    ], v.x);
            fma2(aBb, wB[k/2 + 1], v.y);
        }
        float2 q0, q1;
        q0 = unpack2(aAa); q1 = unpack2(aAb);
        float gA = cA + ((q0.x + q1.x) + (q0.y + q1.y));
        q0 = unpack2(aBa); q1 = unpack2(aBb);
        float gB = cB + ((q0.x + q1.x) + (q0.y + q1.y));

        // rA is i or f -> sigmoid; rB is g (half0 -> tanh) or o (half1 -> sigmoid)
        float aA = fsigmoid(gA);
        float aB = half ? fsigmoid(gB) : ftanh(gB);

        float pA = __shfl_xor_sync(0xffffffffu, aA, 16);
        float pB = __shfl_xor_sync(0xffffffffu, aB, 16);

        // half0: i=aA g=aB f=pA o=pB ; half1: f=aA o=aB i=pA g=pB
        float ig = half ? pA : aA;
        float fg = half ? aA : pA;
        float gg = half ? pB : aB;
        float og = half ? aB : pB;

        float cn = fmaf(fg, creg, ig * gg);
        creg = cn;
        float hn = og * ftanh(cn);
        if (half == 0) hs[pr ^ 1][u] = hn;   // write OTHER parity
        else           yrow[(size_t)t * Hh] = hn;

        __syncthreads();
    }
}

// ---------------------------------------------------------------------------
// Heads (unchanged round 9): occ 4, per-head W staging, packed y in smem.
// ---------------------------------------------------------------------------
__global__ __launch_bounds__(128, 4)
void heads_kernel(const float* __restrict__ y,
                  const float* __restrict__ W1, const float* __restrict__ b1,
                  const float* __restrict__ W2, const float* __restrict__ b2,
                  const float* __restrict__ W3, const float* __restrict__ b3,
                  float* __restrict__ outs)
{
    extern __shared__ float sm[];
    float* w1r = sm;                 // 2048
    float* w2r = w1r + 2048;         // 1024
    float* w3r = w2r + 1024;         // 32
    float* b1r = w3r + 32;           // 32
    float* b2r = b1r + 32;           // 32
    float* b3r = b2r + 32;           // 4 (pad)
    ull*   ysp = (ull*)(sm + 3200);  // [32][129] ull

    const int tid    = threadIdx.x;
    const size_t bt0 = (size_t)blockIdx.x * 128;
    const size_t BT  = (size_t)Bsz * Tt;

    {
        const float4* ysrc = (const float4*)(y + bt0 * Hh);
#pragma unroll
        for (int it = 0; it < 16; it++){
            int i4  = tid + it * 128;
            float4 v = ysrc[i4];
            int bt = i4 >> 4;
            int k2 = (i4 & 15) * 2;
            ysp[(k2    ) * 129 + bt] = pack2(v.x, v.y);
            ysp[(k2 + 1) * 129 + bt] = pack2(v.z, v.w);
        }
    }

    for (int r = 0; r < Rr; r++){
        __syncthreads();
        {
            const float4* s1 = (const float4*)(W1 + r * 2048);
            float4* d1 = (float4*)w1r;
            d1[tid] = s1[tid]; d1[tid+128] = s1[tid+128];
            d1[tid+256] = s1[tid+256]; d1[tid+384] = s1[tid+384];
            const float4* s2 = (const float4*)(W2 + r * 1024);
            float4* d2 = (float4*)w2r;
            d2[tid] = s2[tid]; d2[tid+128] = s2[tid+128];
            if (tid < 8) ((float4*)w3r)[tid] = ((const float4*)(W3 + r * 32))[tid];
            if (tid < 32){ b1r[tid] = b1[r*32 + tid]; b2r[tid] = b2[r*32 + tid]; }
            if (tid == 0) b3r[0] = b3[r];
        }
        __syncthreads();

        ull yv[Hh/2];
#pragma unroll
        for (int k = 0; k < Hh/2; k++) yv[k] = ysp[k * 129 + tid];

        ull h1p[MHh/2];
#pragma unroll
        for (int m = 0; m < MHh; m += 2){
            float hm[2];
#pragma unroll
            for (int mm = 0; mm < 2; mm++){
                const ulonglong2* wp = (const ulonglong2*)(w1r + (m + mm) * Hh);
                ull a0 = 0ULL, a1 = 0ULL, a2 = 0ULL, a3 = 0ULL;
#pragma unroll
                for (int q = 0; q < 8; q++){
                    ulonglong2 wa = wp[2*q    ];
                    ulonglong2 wb = wp[2*q + 1];
                    fma2(a0, wa.x, yv[4*q    ]);
                    fma2(a1, wa.y, yv[4*q + 1]);
                    fma2(a2, wb.x, yv[4*q + 2]);
                    fma2(a3, wb.y, yv[4*q + 3]);
                }
                float2 p0 = unpack2(a0), p1 = unpack2(a1);
                float2 p2 = unpack2(a2), p3 = unpack2(a3);
                float s = ((p0.x + p1.x) + (p0.y + p1.y)) + ((p2.x + p3.x) + (p2.y + p3.y));
                hm[mm] = fmaxf(b1r[m + mm] + s, 0.0f);
            }
            h1p[m/2] = pack2(hm[0], hm[1]);
        }

        ull h2p[MHh/2];
#pragma unroll
        for (int n = 0; n < MHh; n += 2){
            float hv[2];
#pragma unroll
            for (int nn = 0; nn < 2; nn++){
                const ulonglong2* wp = (const ulonglong2*)(w2r + (n + nn) * MHh);
                ull a0 = 0ULL, a1 = 0ULL, a2 = 0ULL, a3 = 0ULL;
#pragma unroll
                for (int q = 0; q < 4; q++){
                    ulonglong2 wa = wp[2*q    ];
                    ulonglong2 wb = wp[2*q + 1];
                    fma2(a0, wa.x, h1p[4*q    ]);
                    fma2(a1, wa.y, h1p[4*q + 1]);
                    fma2(a2, wb.x, h1p[4*q + 2]);
                    fma2(a3, wb.y, h1p[4*q + 3]);
                }
                float2 p0 = unpack2(a0), p1 = unpack2(a1);
                float2 p2 = unpack2(a2), p3 = unpack2(a3);
                float s = ((p0.x + p1.x) + (p0.y + p1.y)) + ((p2.x + p3.x) + (p2.y + p3.y));
                hv[nn] = fmaxf(b2r[n + nn] + s, 0.0f);
            }
            h2p[n/2] = pack2(hv[0], hv[1]);
        }

        {
            const ulonglong2* wp = (const ulonglong2*)w3r;
            ull a0 = 0ULL, a1 = 0ULL, a2 = 0ULL, a3 = 0ULL;
#pragma unroll
            for (int q = 0; q < 4; q++){
                ulonglong2 wa = wp[2*q    ];
                ulonglong2 wb = wp[2*q + 1];
                fma2(a0, wa.x, h2p[4*q    ]);
                fma2(a1, wa.y, h2p[4*q + 1]);
                fma2(a2, wb.x, h2p[4*q + 2]);
                fma2(a3, wb.y, h2p[4*q + 3]);
            }
            float2 p0 = unpack2(a0), p1 = unpack2(a1);
            float2 p2 = unpack2(a2), p3 = unpack2(a3);
            float s = ((p0.x + p1.x) + (p0.y + p1.y)) + ((p2.x + p3.x) + (p2.y + p3.y));
            outs[(size_t)r * BT + bt0 + tid] = b3r[0] + s;
        }
    }
}

extern "C" void kernel_launch(void* const* d_in, const int* in_sizes, int n_in,
                              void* d_out, int out_size)
{
    const float* x      = (const float*)d_in[0];
    const float* h_init = (const float*)d_in[1];
    const float* c_init = (const float*)d_in[2];
    const float* W_ih   = (const float*)d_in[3];
    const float* W_hh   = (const float*)d_in[4];
    const float* b_ih   = (const float*)d_in[5];
    const float* b_hh   = (const float*)d_in[6];
    const float* W1     = (const float*)d_in[7];
    const float* b1     = (const float*)d_in[8];
    const float* W2     = (const float*)d_in[9];
    const float* b2     = (const float*)d_in[10];
    const float* W3     = (const float*)d_in[11];
    const float* b3     = (const float*)d_in[12];

    float* y    = (float*)d_out;                     // (B, T, H)
    float* outs = y + (size_t)Bsz * Tt * Hh;         // (R, B, T)

    proj_kernel<<<Bsz * 4, 128>>>(x, W_ih, b_ih, b_hh);

    lstm_rec_kernel<<<Bsz, 128>>>(h_init, c_init, W_hh, y);

    const size_t shmem = 3200 * sizeof(float) + 32 * 129 * sizeof(ull);  // 45824 B
    cudaFuncSetAttribute(heads_kernel,
                         cudaFuncAttributeMaxDynamicSharedMemorySize, (int)shmem);
    heads_kernel<<<(Bsz * Tt) / 128, 128, shmem>>>(y, W1, b1, W2, b2, W3, b3, outs);
}

// round 11
// speedup vs baseline: 1.5643x; 1.5643x over previous
#include <cuda_runtime.h>
#include <math.h>

#define Bsz 512
#define Tt  1024
#define Dd  64
#define Hh  64
#define Rr  4
#define MHh 32
#define PCH 16

typedef unsigned long long ull;

// xg scratch, plain row order: xg[t][b][row], bias baked in. 512MB.
__device__ float xg_buf[(size_t)Tt * Bsz * 256];

__device__ __forceinline__ void fma2(ull &d, ull a, ull b){
    asm("fma.rn.f32x2 %0, %1, %2, %0;" : "+l"(d) : "l"(a), "l"(b));
}
__device__ __forceinline__ ull pack2(float lo, float hi){
    ull r; asm("mov.b64 %0, {%1, %2};" : "=l"(r) : "f"(lo), "f"(hi)); return r;
}
__device__ __forceinline__ float2 unpack2(ull v){
    float2 r; asm("mov.b64 {%0, %1}, %2;" : "=f"(r.x), "=f"(r.y) : "l"(v)); return r;
}

__device__ __forceinline__ float fsigmoid(float v){
    float e = __expf(-v);
    return __fdividef(1.0f, 1.0f + e);
}
// Saturation-safe: exp argument always <= 0.
__device__ __forceinline__ float ftanh(float v){
    float t = __expf(-2.0f * fabsf(v));
    float r = __fdividef(1.0f - t, 1.0f + t);
    return copysignf(r, v);
}

// ---------------------------------------------------------------------------
// Input projection (unchanged): thread j owns rows 2j, 2j+1.
// ---------------------------------------------------------------------------
__global__ __launch_bounds__(128)
void proj_kernel(const float* __restrict__ x,
                 const float* __restrict__ W_ih,
                 const float* __restrict__ b_ih,
                 const float* __restrict__ b_hh)
{
    const int j  = threadIdx.x;
    const int r0 = 2*j, r1 = 2*j + 1;
    const int b  = blockIdx.x >> 2;
    const int t0 = (blockIdx.x & 3) * 256;

    __shared__ __align__(16) float xsh[PCH][Dd];

    ull w0[Dd/2], w1[Dd/2];
#pragma unroll
    for (int k = 0; k < Dd/2; k += 2){
        ulonglong2 a = *(const ulonglong2*)&W_ih[r0 * Dd + 2*k];
        w0[k] = a.x; w0[k+1] = a.y;
        ulonglong2 c = *(const ulonglong2*)&W_ih[r1 * Dd + 2*k];
        w1[k] = c.x; w1[k+1] = c.y;
    }
    const float bj0 = b_ih[r0] + b_hh[r0];
    const float bj1 = b_ih[r1] + b_hh[r1];

    for (int c0 = 0; c0 < 256; c0 += PCH){
        const float4* src = (const float4*)(x + ((size_t)b * Tt + t0 + c0) * Dd);
        float4* dst = (float4*)&xsh[0][0];
        dst[j] = src[j];
        dst[j + 128] = src[j + 128];
        __syncthreads();

#pragma unroll 2
        for (int p = 0; p < PCH; p++){
            const ulonglong2* v = (const ulonglong2*)&xsh[p][0];
            ull a00 = 0ULL, a01 = 0ULL, a10 = 0ULL, a11 = 0ULL;
#pragma unroll
            for (int q = 0; q < 16; q++){
                ulonglong2 xx = v[q];
                fma2(a00, w0[2*q    ], xx.x);
                fma2(a01, w0[2*q + 1], xx.y);
                fma2(a10, w1[2*q    ], xx.x);
                fma2(a11, w1[2*q + 1], xx.y);
            }
            float2 p0 = unpack2(a00), p1 = unpack2(a01);
            float2 p2 = unpack2(a10), p3 = unpack2(a11);
            size_t base = ((size_t)(t0 + c0 + p) * Bsz + b) * 256;
            float2 o;
            o.x = bj0 + ((p0.x + p1.x) + (p0.y + p1.y));
            o.y = bj1 + ((p2.x + p3.x) + (p2.y + p3.y));
            *(float2*)&xg_buf[base + 2*j] = o;
        }
        __syncthreads();
    }
}

// ---------------------------------------------------------------------------
// Recurrence v4b: 512 blocks x 128 threads, ONE batch per block, occupancy 4
// (128-reg cap: NO spills — round 10's (128,8) forced a 64-reg cap and
// spilled the weight arrays). Warp w covers units 16w..16w+15.
// Lane l<16: rows (i,g) of unit u. Lane l>=16: rows (f,o) of same unit.
// Gate exchange = 2x shfl_xor(16); both halves compute the identical state
// update; half0 stores hs (double-buffered), half1 stores y.
// ONE __syncthreads per step.
// ---------------------------------------------------------------------------
__global__ __launch_bounds__(128, 4)
void lstm_rec_kernel(const float* __restrict__ h_init,
                     const float* __restrict__ c_init,
                     const float* __restrict__ W_hh,
                     float* __restrict__ y)
{
    const int tid  = threadIdx.x;
    const int w    = tid >> 5;
    const int l    = tid & 31;
    const int half = l >> 4;               // 0: rows (i,g); 1: rows (f,o)
    const int u    = (w << 4) + (l & 15);  // unit 0..63
    const int rA   = half ? (64 + u) : u;          // f : i
    const int rB   = half ? (192 + u) : (128 + u); // o : g
    const int b    = blockIdx.x;            // batch

    __shared__ __align__(16) float hs[2][Hh];

    ull wA[Hh/2], wB[Hh/2];
#pragma unroll
    for (int k = 0; k < Hh/2; k += 2){
        ulonglong2 a = *(const ulonglong2*)&W_hh[rA * Hh + 2*k];
        wA[k] = a.x; wA[k+1] = a.y;
        ulonglong2 c = *(const ulonglong2*)&W_hh[rB * Hh + 2*k];
        wB[k] = c.x; wB[k+1] = c.y;
    }

    float creg = c_init[u];                // state (unit u) — kept by BOTH halves
    if (half == 0) hs[0][u] = h_init[u];

    float xA = xg_buf[(size_t)b * 256 + rA];
    float xB = xg_buf[(size_t)b * 256 + rB];
    __syncthreads();

    float* yrow = y + (size_t)b * Tt * Hh + u;

#pragma unroll 1
    for (int t = 0; t < Tt; t++){
        const int pr = t & 1;
        float cA = xA, cB = xB;
        if (t + 1 < Tt){
            size_t base = ((size_t)(t + 1) * Bsz + b) * 256;
            xA = xg_buf[base + rA];
            xB = xg_buf[base + rB];
        }

        ull aAa = 0ULL, aAb = 0ULL, aBa = 0ULL, aBb = 0ULL;
#pragma unroll
        for (int k = 0; k < Hh; k += 4){
            ulonglong2 v = *(const ulonglong2*)&hs[pr][k];   // broadcast LDS.128
            fma2(aAa, wA[k/2    ], v.x);
            fma2(aAb, wA[k/2 + 1], v.y);
            fma2(aBa, wB[k/2    ], v.x);
            fma2(aBb, wB[k/2 + 1], v.y);
        }
        float2 q0, q1;
        q0 = unpack2(aAa); q1 = unpack2(aAb);
        float gA = cA + ((q0.x + q1.x) + (q0.y + q1.y));
        q0 = unpack2(aBa); q1 = unpack2(aBb);
        float gB = cB + ((q0.x + q1.x) + (q0.y + q1.y));

        // rA is i or f -> sigmoid; rB is g (half0 -> tanh) or o (half1 -> sigmoid)
        float aA = fsigmoid(gA);
        float aB = half ? fsigmoid(gB) : ftanh(gB);

        float pA = __shfl_xor_sync(0xffffffffu, aA, 16);
        float pB = __shfl_xor_sync(0xffffffffu, aB, 16);

        // half0: i=aA g=aB f=pA o=pB ; half1: f=aA o=aB i=pA g=pB
        float ig = half ? pA : aA;
        float fg = half ? aA : pA;
        float gg = half ? pB : aB;
        float og = half ? aB : pB;

        float cn = fmaf(fg, creg, ig * gg);
        creg = cn;
        float hn = og * ftanh(cn);
        if (half == 0) hs[pr ^ 1][u] = hn;   // write OTHER parity
        else           yrow[(size_t)t * Hh] = hn;

        __syncthreads();
    }
}

// ---------------------------------------------------------------------------
// Heads (unchanged): occ 4, per-head W staging, packed y in smem.
// ---------------------------------------------------------------------------
__global__ __launch_bounds__(128, 4)
void heads_kernel(const float* __restrict__ y,
                  const float* __restrict__ W1, const float* __restrict__ b1,
                  const float* __restrict__ W2, const float* __restrict__ b2,
                  const float* __restrict__ W3, const float* __restrict__ b3,
                  float* __restrict__ outs)
{
    extern __shared__ float sm[];
    float* w1r = sm;                 // 2048
    float* w2r = w1r + 2048;         // 1024
    float* w3r = w2r + 1024;         // 32
    float* b1r = w3r + 32;           // 32
    float* b2r = b1r + 32;           // 32
    float* b3r = b2r + 32;           // 4 (pad)
    ull*   ysp = (ull*)(sm + 3200);  // [32][129] ull

    const int tid    = threadIdx.x;
    const size_t bt0 = (size_t)blockIdx.x * 128;
    const size_t BT  = (size_t)Bsz * Tt;

    {
        const float4* ysrc = (const float4*)(y + bt0 * Hh);
#pragma unroll
        for (int it = 0; it < 16; it++){
            int i4  = tid + it * 128;
            float4 v = ysrc[i4];
            int bt = i4 >> 4;
            int k2 = (i4 & 15) * 2;
            ysp[(k2    ) * 129 + bt] = pack2(v.x, v.y);
            ysp[(k2 + 1) * 129 + bt] = pack2(v.z, v.w);
        }
    }

    for (int r = 0; r < Rr; r++){
        __syncthreads();
        {
            const float4* s1 = (const float4*)(W1 + r * 2048);
            float4* d1 = (float4*)w1r;
            d1[tid] = s1[tid]; d1[tid+128] = s1[tid+128];
            d1[tid+256] = s1[tid+256]; d1[tid+384] = s1[tid+384];
            const float4* s2 = (const float4*)(W2 + r * 1024);
            float4* d2 = (float4*)w2r;
            d2[tid] = s2[tid]; d2[tid+128] = s2[tid+128];
            if (tid < 8) ((float4*)w3r)[tid] = ((const float4*)(W3 + r * 32))[tid];
            if (tid < 32){ b1r[tid] = b1[r*32 + tid]; b2r[tid] = b2[r*32 + tid]; }
            if (tid == 0) b3r[0] = b3[r];
        }
        __syncthreads();

        ull yv[Hh/2];
#pragma unroll
        for (int k = 0; k < Hh/2; k++) yv[k] = ysp[k * 129 + tid];

        ull h1p[MHh/2];
#pragma unroll
        for (int m = 0; m < MHh; m += 2){
            float hm[2];
#pragma unroll
            for (int mm = 0; mm < 2; mm++){
                const ulonglong2* wp = (const ulonglong2*)(w1r + (m + mm) * Hh);
                ull a0 = 0ULL, a1 = 0ULL, a2 = 0ULL, a3 = 0ULL;
#pragma unroll
                for (int q = 0; q < 8; q++){
                    ulonglong2 wa = wp[2*q    ];
                    ulonglong2 wb = wp[2*q + 1];
                    fma2(a0, wa.x, yv[4*q    ]);
                    fma2(a1, wa.y, yv[4*q + 1]);
                    fma2(a2, wb.x, yv[4*q + 2]);
                    fma2(a3, wb.y, yv[4*q + 3]);
                }
                float2 p0 = unpack2(a0), p1 = unpack2(a1);
                float2 p2 = unpack2(a2), p3 = unpack2(a3);
                float s = ((p0.x + p1.x) + (p0.y + p1.y)) + ((p2.x + p3.x) + (p2.y + p3.y));
                hm[mm] = fmaxf(b1r[m + mm] + s, 0.0f);
            }
            h1p[m/2] = pack2(hm[0], hm[1]);
        }

        ull h2p[MHh/2];
#pragma unroll
        for (int n = 0; n < MHh; n += 2){
            float hv[2];
#pragma unroll
            for (int nn = 0; nn < 2; nn++){
                const ulonglong2* wp = (const ulonglong2*)(w2r + (n + nn) * MHh);
                ull a0 = 0ULL, a1 = 0ULL, a2 = 0ULL, a3 = 0ULL;
#pragma unroll
                for (int q = 0; q < 4; q++){
                    ulonglong2 wa = wp[2*q    ];
                    ulonglong2 wb = wp[2*q + 1];
                    fma2(a0, wa.x, h1p[4*q    ]);
                    fma2(a1, wa.y, h1p[4*q + 1]);
                    fma2(a2, wb.x, h1p[4*q + 2]);
                    fma2(a3, wb.y, h1p[4*q + 3]);
                }
                float2 p0 = unpack2(a0), p1 = unpack2(a1);
                float2 p2 = unpack2(a2), p3 = unpack2(a3);
                float s = ((p0.x + p1.x) + (p0.y + p1.y)) + ((p2.x + p3.x) + (p2.y + p3.y));
                hv[nn] = fmaxf(b2r[n + nn] + s, 0.0f);
            }
            h2p[n/2] = pack2(hv[0], hv[1]);
        }

        {
            const ulonglong2* wp = (const ulonglong2*)w3r;
            ull a0 = 0ULL, a1 = 0ULL, a2 = 0ULL, a3 = 0ULL;
#pragma unroll
            for (int q = 0; q < 4; q++){
                ulonglong2 wa = wp[2*q    ];
                ulonglong2 wb = wp[2*q + 1];
                fma2(a0, wa.x, h2p[4*q    ]);
                fma2(a1, wa.y, h2p[4*q + 1]);
                fma2(a2, wb.x, h2p[4*q + 2]);
                fma2(a3, wb.y, h2p[4*q + 3]);
            }
            float2 p0 = unpack2(a0), p1 = unpack2(a1);
            float2 p2 = unpack2(a2), p3 = unpack2(a3);
            float s = ((p0.x + p1.x) + (p0.y + p1.y)) + ((p2.x + p3.x) + (p2.y + p3.y));
            outs[(size_t)r * BT + bt0 + tid] = b3r[0] + s;
        }
    }
}

extern "C" void kernel_launch(void* const* d_in, const int* in_sizes, int n_in,
                              void* d_out, int out_size)
{
    const float* x      = (const float*)d_in[0];
    const float* h_init = (const float*)d_in[1];
    const float* c_init = (const float*)d_in[2];
    const float* W_ih   = (const float*)d_in[3];
    const float* W_hh   = (const float*)d_in[4];
    const float* b_ih   = (const float*)d_in[5];
    const float* b_hh   = (const float*)d_in[6];
    const float* W1     = (const float*)d_in[7];
    const float* b1     = (const float*)d_in[8];
    const float* W2     = (const float*)d_in[9];
    const float* b2     = (const float*)d_in[10];
    const float* W3     = (const float*)d_in[11];
    const float* b3     = (const float*)d_in[12];

    float* y    = (float*)d_out;                     // (B, T, H)
    float* outs = y + (size_t)Bsz * Tt * Hh;         // (R, B, T)

    proj_kernel<<<Bsz * 4, 128>>>(x, W_ih, b_ih, b_hh);

    lstm_rec_kernel<<<Bsz, 128>>>(h_init, c_init, W_hh, y);

    const size_t shmem = 3200 * sizeof(float) + 32 * 129 * sizeof(ull);  // 45824 B
    cudaFuncSetAttribute(heads_kernel,
                         cudaFuncAttributeMaxDynamicSharedMemorySize, (int)shmem);
    heads_kernel<<<(Bsz * Tt) / 128, 128, shmem>>>(y, W1, b1, W2, b2, W3, b3, outs);
}

// round 12
// speedup vs baseline: 2.5710x; 1.6435x over previous
#include <cuda_runtime.h>
#include <math.h>

#define Bsz 512
#define Tt  1024
#define Dd  64
#define Hh  64
#define Rr  4
#define MHh 32
#define PCH 16

typedef unsigned long long ull;

// xg scratch, plain row order: xg[t][b][row], bias baked in. 512MB.
__device__ float xg_buf[(size_t)Tt * Bsz * 256];

__device__ __forceinline__ void fma2(ull &d, ull a, ull b){
    asm("fma.rn.f32x2 %0, %1, %2, %0;" : "+l"(d) : "l"(a), "l"(b));
}
__device__ __forceinline__ ull pack2(float lo, float hi){
    ull r; asm("mov.b64 %0, {%1, %2};" : "=l"(r) : "f"(lo), "f"(hi)); return r;
}
__device__ __forceinline__ float2 unpack2(ull v){
    float2 r; asm("mov.b64 {%0, %1}, %2;" : "=f"(r.x), "=f"(r.y) : "l"(v)); return r;
}

__device__ __forceinline__ float fsigmoid(float v){
    float e = __expf(-v);
    return __fdividef(1.0f, 1.0f + e);
}
// Saturation-safe: exp argument always <= 0.
__device__ __forceinline__ float ftanh(float v){
    float t = __expf(-2.0f * fabsf(v));
    float r = __fdividef(1.0f - t, 1.0f + t);
    return copysignf(r, v);
}

// ---------------------------------------------------------------------------
// Input projection v4: 2 rows/thread (rows 2j, 2j+1), DOUBLE-BUFFERED x
// staging: prefetch chunk c+1 to regs during compute of c, one barrier/chunk.
// ---------------------------------------------------------------------------
__global__ __launch_bounds__(128)
void proj_kernel(const float* __restrict__ x,
                 const float* __restrict__ W_ih,
                 const float* __restrict__ b_ih,
                 const float* __restrict__ b_hh)
{
    const int j  = threadIdx.x;
    const int r0 = 2*j, r1 = 2*j + 1;
    const int b  = blockIdx.x >> 2;
    const int t0 = (blockIdx.x & 3) * 256;

    __shared__ __align__(16) float xsh[2][PCH][Dd];

    ull w0[Dd/2], w1[Dd/2];
#pragma unroll
    for (int k = 0; k < Dd/2; k += 2){
        ulonglong2 a = *(const ulonglong2*)&W_ih[r0 * Dd + 2*k];
        w0[k] = a.x; w0[k+1] = a.y;
        ulonglong2 c = *(const ulonglong2*)&W_ih[r1 * Dd + 2*k];
        w1[k] = c.x; w1[k+1] = c.y;
    }
    const float bj0 = b_ih[r0] + b_hh[r0];
    const float bj1 = b_ih[r1] + b_hh[r1];

    const float4* xbase = (const float4*)(x + ((size_t)b * Tt + t0) * Dd);
    const int CHUNK4 = PCH * Dd / 4;       // 256 float4 per chunk

    // prologue: stage chunk 0 into buffer 0
    {
        float4 pa = xbase[j], pb = xbase[j + 128];
        float4* dst = (float4*)&xsh[0][0][0];
        dst[j] = pa; dst[j + 128] = pb;
    }
    __syncthreads();

    for (int c = 0; c < 256 / PCH; c++){
        const int pb_ = c & 1;
        // prefetch chunk c+1 into registers (overlapped with compute)
        float4 pa, pbv;
        if (c + 1 < 256 / PCH){
            const float4* src = xbase + (size_t)(c + 1) * CHUNK4;
            pa  = src[j];
            pbv = src[j + 128];
        }

#pragma unroll 4
        for (int p = 0; p < PCH; p++){
            const ulonglong2* v = (const ulonglong2*)&xsh[pb_][p][0];
            ull a00 = 0ULL, a01 = 0ULL, a10 = 0ULL, a11 = 0ULL;
#pragma unroll
            for (int q = 0; q < 16; q++){
                ulonglong2 xx = v[q];              // broadcast LDS.128
                fma2(a00, w0[2*q    ], xx.x);
                fma2(a01, w0[2*q + 1], xx.y);
                fma2(a10, w1[2*q    ], xx.x);
                fma2(a11, w1[2*q + 1], xx.y);
            }
            float2 p0 = unpack2(a00), p1 = unpack2(a01);
            float2 p2 = unpack2(a10), p3 = unpack2(a11);
            size_t base = ((size_t)(t0 + c * PCH + p) * Bsz + b) * 256;
            float2 o;
            o.x = bj0 + ((p0.x + p1.x) + (p0.y + p1.y));
            o.y = bj1 + ((p2.x + p3.x) + (p2.y + p3.y));
            *(float2*)&xg_buf[base + 2*j] = o;     // STG.64
        }

        if (c + 1 < 256 / PCH){
            float4* dst = (float4*)&xsh[pb_ ^ 1][0][0];
            dst[j] = pa; dst[j + 128] = pbv;       // fill other parity
        }
        __syncthreads();
    }
}

// ---------------------------------------------------------------------------
// Recurrence v3 (round-9 exact revert — best measured ~650us):
// 256 blocks x 128 thr, 2 batches/block, 2 blocks/SM. Lane l<16: rows (i,g)
// of unit u, owns batch0 state; lane l>=16: rows (f,o), owns batch1 state.
// Gate exchange = 4x shfl_xor(16). hs double-buffered, ONE barrier/step.
// ---------------------------------------------------------------------------
__global__ __launch_bounds__(128, 2)
void lstm_rec_kernel(const float* __restrict__ h_init,
                     const float* __restrict__ c_init,
                     const float* __restrict__ W_hh,
                     float* __restrict__ y)
{
    const int tid  = threadIdx.x;
    const int w    = tid >> 5;
    const int l    = tid & 31;
    const int half = l >> 4;               // 0: (i,g)+batch0, 1: (f,o)+batch1
    const int u    = (w << 4) + (l & 15);  // unit 0..63
    const int rA   = half ? (64 + u) : u;          // f : i
    const int rB   = half ? (192 + u) : (128 + u); // o : g
    const int b0   = blockIdx.x * 2;

    __shared__ __align__(16) float hs[2][2][Hh];

    ull wA[Hh/2], wB[Hh/2];
#pragma unroll
    for (int k = 0; k < Hh/2; k += 2){
        ulonglong2 a = *(const ulonglong2*)&W_hh[rA * Hh + 2*k];
        wA[k] = a.x; wA[k+1] = a.y;
        ulonglong2 c = *(const ulonglong2*)&W_hh[rB * Hh + 2*k];
        wB[k] = c.x; wB[k+1] = c.y;
    }

    float creg = c_init[u];                // state (batch = half, unit = u)
    hs[0][half][u] = h_init[u];

    float xA0 = xg_buf[(size_t)(b0    ) * 256 + rA];
    float xB0 = xg_buf[(size_t)(b0    ) * 256 + rB];
    float xA1 = xg_buf[(size_t)(b0 + 1) * 256 + rA];
    float xB1 = xg_buf[(size_t)(b0 + 1) * 256 + rB];
    __syncthreads();

#pragma unroll 1
    for (int t = 0; t < Tt; t++){
        const int pr = t & 1;
        float cA0 = xA0, cB0 = xB0, cA1 = xA1, cB1 = xB1;
        if (t + 1 < Tt){
            size_t base = ((size_t)(t + 1) * Bsz + b0) * 256;
            xA0 = xg_buf[base + rA];
            xB0 = xg_buf[base + rB];
            xA1 = xg_buf[base + 256 + rA];
            xB1 = xg_buf[base + 256 + rB];
        }

        ull aA0a=0,aA0b=0,aB0a=0,aB0b=0,aA1a=0,aA1b=0,aB1a=0,aB1b=0;
#pragma unroll
        for (int k = 0; k < Hh; k += 4){
            ulonglong2 v0 = *(const ulonglong2*)&hs[pr][0][k];
            ulonglong2 v1 = *(const ulonglong2*)&hs[pr][1][k];
            fma2(aA0a, wA[k/2    ], v0.x);
            fma2(aA0b, wA[k/2 + 1], v0.y);
            fma2(aB0a, wB[k/2    ], v0.x);
            fma2(aB0b, wB[k/2 + 1], v0.y);
            fma2(aA1a, wA[k/2    ], v1.x);
            fma2(aA1b, wA[k/2 + 1], v1.y);
            fma2(aB1a, wB[k/2    ], v1.x);
            fma2(aB1b, wB[k/2 + 1], v1.y);
        }
        float2 q0, q1;
        q0 = unpack2(aA0a); q1 = unpack2(aA0b);
        float gA0 = cA0 + ((q0.x + q1.x) + (q0.y + q1.y));
        q0 = unpack2(aB0a); q1 = unpack2(aB0b);
        float gB0 = cB0 + ((q0.x + q1.x) + (q0.y + q1.y));
        q0 = unpack2(aA1a); q1 = unpack2(aA1b);
        float gA1 = cA1 + ((q0.x + q1.x) + (q0.y + q1.y));
        q0 = unpack2(aB1a); q1 = unpack2(aB1b);
        float gB1 = cB1 + ((q0.x + q1.x) + (q0.y + q1.y));

        float aA0 = fsigmoid(gA0);
        float aA1 = fsigmoid(gA1);
        float aB0 = half ? fsigmoid(gB0) : ftanh(gB0);
        float aB1 = half ? fsigmoid(gB1) : ftanh(gB1);

        float pA0 = __shfl_xor_sync(0xffffffffu, aA0, 16);
        float pB0 = __shfl_xor_sync(0xffffffffu, aB0, 16);
        float pA1 = __shfl_xor_sync(0xffffffffu, aA1, 16);
        float pB1 = __shfl_xor_sync(0xffffffffu, aB1, 16);

        float ig = half ? pA1 : aA0;
        float fg = half ? aA1 : pA0;
        float gg = half ? pB1 : aB0;
        float og = half ? aB1 : pB0;

        float cn = fmaf(fg, creg, ig * gg);
        creg = cn;
        float hn = og * ftanh(cn);
        hs[pr ^ 1][half][u] = hn;
        y[((size_t)(b0 + half)) * Tt * Hh + (size_t)t * Hh + u] = hn;

        __syncthreads();
    }
}

// ---------------------------------------------------------------------------
// Heads (round-9 exact): occ 4, per-head W staging, packed y in smem.
// ---------------------------------------------------------------------------
__global__ __launch_bounds__(128, 4)
void heads_kernel(const float* __restrict__ y,
                  const float* __restrict__ W1, const float* __restrict__ b1,
                  const float* __restrict__ W2, const float* __restrict__ b2,
                  const float* __restrict__ W3, const float* __restrict__ b3,
                  float* __restrict__ outs)
{
    extern __shared__ float sm[];
    float* w1r = sm;                 // 2048
    float* w2r = w1r + 2048;         // 1024
    float* w3r = w2r + 1024;         // 32
    float* b1r = w3r + 32;           // 32
    float* b2r = b1r + 32;           // 32
    float* b3r = b2r + 32;           // 4 (pad)
    ull*   ysp = (ull*)(sm + 3200);  // [32][129] ull

    const int tid    = threadIdx.x;
    const size_t bt0 = (size_t)blockIdx.x * 128;
    const size_t BT  = (size_t)Bsz * Tt;

    {
        const float4* ysrc = (const float4*)(y + bt0 * Hh);
#pragma unroll
        for (int it = 0; it < 16; it++){
            int i4  = tid + it * 128;
            float4 v = ysrc[i4];
            int bt = i4 >> 4;
            int k2 = (i4 & 15) * 2;
            ysp[(k2    ) * 129 + bt] = pack2(v.x, v.y);
            ysp[(k2 + 1) * 129 + bt] = pack2(v.z, v.w);
        }
    }

    for (int r = 0; r < Rr; r++){
        __syncthreads();
        {
            const float4* s1 = (const float4*)(W1 + r * 2048);
            float4* d1 = (float4*)w1r;
            d1[tid] = s1[tid]; d1[tid+128] = s1[tid+128];
            d1[tid+256] = s1[tid+256]; d1[tid+384] = s1[tid+384];
            const float4* s2 = (const float4*)(W2 + r * 1024);
            float4* d2 = (float4*)w2r;
            d2[tid] = s2[tid]; d2[tid+128] = s2[tid+128];
            if (tid < 8) ((float4*)w3r)[tid] = ((const float4*)(W3 + r * 32))[tid];
            if (tid < 32){ b1r[tid] = b1[r*32 + tid]; b2r[tid] = b2[r*32 + tid]; }
            if (tid == 0) b3r[0] = b3[r];
        }
        __syncthreads();

        ull yv[Hh/2];
#pragma unroll
        for (int k = 0; k < Hh/2; k++) yv[k] = ysp[k * 129 + tid];

        ull h1p[MHh/2];
#pragma unroll
        for (int m = 0; m < MHh; m += 2){
            float hm[2];
#pragma unroll
            for (int mm = 0; mm < 2; mm++){
                const ulonglong2* wp = (const ulonglong2*)(w1r + (m + mm) * Hh);
                ull a0 = 0ULL, a1 = 0ULL, a2 = 0ULL, a3 = 0ULL;
#pragma unroll
                for (int q = 0; q < 8; q++){
                    ulonglong2 wa = wp[2*q    ];
                    ulonglong2 wb = wp[2*q + 1];
                    fma2(a0, wa.x, yv[4*q    ]);
                    fma2(a1, wa.y, yv[4*q + 1]);
                    fma2(a2, wb.x, yv[4*q + 2]);
                    fma2(a3, wb.y, yv[4*q + 3]);
                }
                float2 p0 = unpack2(a0), p1 = unpack2(a1);
                float2 p2 = unpack2(a2), p3 = unpack2(a3);
                float s = ((p0.x + p1.x) + (p0.y + p1.y)) + ((p2.x + p3.x) + (p2.y + p3.y));
                hm[mm] = fmaxf(b1r[m + mm] + s, 0.0f);
            }
            h1p[m/2] = pack2(hm[0], hm[1]);
        }

        ull h2p[MHh/2];
#pragma unroll
        for (int n = 0; n < MHh; n += 2){
            float hv[2];
#pragma unroll
            for (int nn = 0; nn < 2; nn++){
                const ulonglong2* wp = (const ulonglong2*)(w2r + (n + nn) * MHh);
                ull a0 = 0ULL, a1 = 0ULL, a2 = 0ULL, a3 = 0ULL;
#pragma unroll
                for (int q = 0; q < 4; q++){
                    ulonglong2 wa = wp[2*q    ];
                    ulonglong2 wb = wp[2*q + 1];
                    fma2(a0, wa.x, h1p[4*q    ]);
                    fma2(a1, wa.y, h1p[4*q + 1]);
                    fma2(a2, wb.x, h1p[4*q + 2]);
                    fma2(a3, wb.y, h1p[4*q + 3]);
                }
                float2 p0 = unpack2(a0), p1 = unpack2(a1);
                float2 p2 = unpack2(a2), p3 = unpack2(a3);
                float s = ((p0.x + p1.x) + (p0.y + p1.y)) + ((p2.x + p3.x) + (p2.y + p3.y));
                hv[nn] = fmaxf(b2r[n + nn] + s, 0.0f);
            }
            h2p[n/2] = pack2(hv[0], hv[1]);
        }

        {
            const ulonglong2* wp = (const ulonglong2*)w3r;
            ull a0 = 0ULL, a1 = 0ULL, a2 = 0ULL, a3 = 0ULL;
#pragma unroll
            for (int q = 0; q < 4; q++){
                ulonglong2 wa = wp[2*q    ];
                ulonglong2 wb = wp[2*q + 1];
                fma2(a0, wa.x, h2p[4*q    ]);
                fma2(a1, wa.y, h2p[4*q + 1]);
                fma2(a2, wb.x, h2p[4*q + 2]);
                fma2(a3, wb.y, h2p[4*q + 3]);
            }
            float2 p0 = unpack2(a0), p1 = unpack2(a1);
            float2 p2 = unpack2(a2), p3 = unpack2(a3);
            float s = ((p0.x + p1.x) + (p0.y + p1.y)) + ((p2.x + p3.x) + (p2.y + p3.y));
            outs[(size_t)r * BT + bt0 + tid] = b3r[0] + s;
        }
    }
}

extern "C" void kernel_launch(void* const* d_in, const int* in_sizes, int n_in,
                              void* d_out, int out_size)
{
    const float* x      = (const float*)d_in[0];
    const float* h_init = (const float*)d_in[1];
    const float* c_init = (const float*)d_in[2];
    const float* W_ih   = (const float*)d_in[3];
    const float* W_hh   = (const float*)d_in[4];
    const float* b_ih   = (const float*)d_in[5];
    const float* b_hh   = (const float*)d_in[6];
    const float* W1     = (const float*)d_in[7];
    const float* b1     = (const float*)d_in[8];
    const float* W2     = (const float*)d_in[9];
    const float* b2     = (const float*)d_in[10];
    const float* W3     = (const float*)d_in[11];
    const float* b3     = (const float*)d_in[12];

    float* y    = (float*)d_out;                     // (B, T, H)
    float* outs = y + (size_t)Bsz * Tt * Hh;         // (R, B, T)

    proj_kernel<<<Bsz * 4, 128>>>(x, W_ih, b_ih, b_hh);

    lstm_rec_kernel<<<Bsz / 2, 128>>>(h_init, c_init, W_hh, y);

    const size_t shmem = 3200 * sizeof(float) + 32 * 129 * sizeof(ull);  // 45824 B
    cudaFuncSetAttribute(heads_kernel,
                         cudaFuncAttributeMaxDynamicSharedMemorySize, (int)shmem);
    heads_kernel<<<(Bsz * Tt) / 128, 128, shmem>>>(y, W1, b1, W2, b2, W3, b3, outs);
}